// round 3
// baseline (speedup 1.0000x reference)
#include <cuda_runtime.h>
#include <cuda_bf16.h>

// Cost volume: out[n,c,d,h,w] = left[n,c,h,w] * right[n,c,h,w-d]  (0 if w<d)
// N=2 C=32 H=136 W=240 D=48, fp32.
//
// R2 analysis: L1 pipe co-limits with DRAM (2 l1tex wavefronts per 128B out:
// 1 LDS + 1 STG). Fix: each warp's 80-float right-row window lives in 3
// registers/thread; shifted operands come from warp shuffles (no l1tex
// traffic). L1 drops to store-only -> DRAM becomes sole limiter.

#define NW 240
#define NH 136
#define NC 32
#define NN 2
#define ND 48
#define THREADS 256

// Padded right row P[x] = right[row][x] for 0<=x<240, else 0.
// Register window per warp (base wb): h0=P[wb+lane-64], h1=P[wb+lane-32], h2=P[wb+lane].
// buf[i] holds P[i-80], i in [0,336).
#define BUFSZ (80 + NW + 16)   // 336: covers P[-80 .. 256)

__global__ __launch_bounds__(THREADS, 8)
void cost_volume_kernel(const float* __restrict__ left,
                        const float* __restrict__ right,
                        float* __restrict__ out) {
    __shared__ float buf[BUFSZ];

    const int row  = blockIdx.x;         // row = nc * NH + h
    const int h    = row % NH;
    const int nc   = row / NH;
    const int tid  = threadIdx.x;
    const int lane = tid & 31;

    const float* rrow = right + (size_t)row * NW;
    for (int i = tid; i < BUFSZ; i += THREADS)
        buf[i] = (i >= 80 && i < 80 + NW) ? rrow[i - 80] : 0.0f;
    __syncthreads();

    const int  w   = tid;                // column; >=240 lanes are store-inactive
    const bool act = (w < NW);
    const float l  = act ? left[(size_t)row * NW + w] : 0.0f;

    // 3 conflict-free LDS (lane-stride 1) -> whole 80-float window in registers.
    const float h0 = buf[16 + w];        // P[w-64]
    const float h1 = buf[48 + w];        // P[w-32]
    const float h2 = buf[80 + w];        // P[w]

    float* optr = out + ((size_t)nc * ND * NH + h) * NW + w;

    #pragma unroll
    for (int d = 0; d < ND; d++) {
        const int sl = (lane - d) & 31;
        float v;
        if (d == 0) {
            v = h2;
        } else if (d < 32) {
            // P[w-d]: lanes >= d take it from h2 (own warp window),
            // lanes < d wrap into the h1 window. Same source lane for both.
            const float a = __shfl_sync(0xFFFFFFFFu, h2, sl);
            const float b = __shfl_sync(0xFFFFFFFFu, h1, sl);
            v = (lane >= d) ? a : b;
        } else {
            const float a = __shfl_sync(0xFFFFFFFFu, h1, sl);
            const float b = __shfl_sync(0xFFFFFFFFu, h0, sl);
            v = (lane >= d - 32) ? a : b;
        }
        if (act)
            optr[(size_t)d * (NH * NW)] = l * v;
    }
}

extern "C" void kernel_launch(void* const* d_in, const int* in_sizes, int n_in,
                              void* d_out, int out_size) {
    const float* left  = (const float*)d_in[0];
    const float* right = (const float*)d_in[1];
    float* out = (float*)d_out;

    const int grid = NN * NC * NH;       // 8704 CTAs, one per (n,c,h) row
    cost_volume_kernel<<<grid, THREADS>>>(left, right, out);
}

// round 4
// speedup vs baseline: 1.1400x; 1.1400x over previous
#include <cuda_runtime.h>
#include <cuda_bf16.h>

// Cost volume: out[n,c,d,h,w] = left[n,c,h,w] * right[n,c,h,w-d]  (0 if w<d)
// N=2 C=32 H=136 W=240 D=48, fp32.
//
// R3 lesson: SHFL counts as l1tex traffic (LSU pipe) -> no win over LDS.
// R4: amortize LSU ops. For d = 4q+s, all 4 products per thread need only
// components of two ALIGNED float4s X=P4[c-q-1], Y=P4[c-q] (P zero-padded).
// => 2 LDS.128 serve 4 disparities; stores are STG.128 (streaming, __stcs).
// l1tex wavefronts per KB drop ~16 -> ~9; DRAM write stream becomes limiter.

#define NW   240
#define NH   136
#define NC   32
#define NN   2
#define ND   48
#define W4   60              // float4 columns per row
#define PADF 64              // zero floats in front of P (covers 4(c-q-1) >= -48)
#define THREADS 256

__global__ __launch_bounds__(THREADS, 8)
void cost_volume_kernel(const float* __restrict__ left,
                        const float* __restrict__ right,
                        float* __restrict__ out) {
    // buf[i] = P[i - PADF]; P[x] = rrow[x] for 0<=x<240, 0 for x<0.
    __shared__ __align__(16) float buf[PADF + NW];

    const int row  = blockIdx.x;         // row = nc * NH + h
    const int h    = row % NH;
    const int nc   = row / NH;
    const int tid  = threadIdx.x;
    const int lane = tid & 31;
    const int wid  = tid >> 5;           // 0..7

    const float* rrow = right + (size_t)row * NW;
    for (int i = tid; i < PADF + NW; i += THREADS)
        buf[i] = (i < PADF) ? 0.0f : rrow[i - PADF];
    __syncthreads();

    // 8 warps: [wid&1] selects column half, [wid>>1] selects d-stripe (12 d's).
    const int c      = lane + ((wid & 1) << 5);   // float4 column 0..63
    const int stripe = wid >> 1;                  // 0..3
    if (c >= W4) return;                          // no collectives below

    const float4 l4 = reinterpret_cast<const float4*>(left + (size_t)row * NW)[c];

    float* obase = out + ((size_t)nc * ND * NH + h) * NW + 4 * c;
    const float* P = buf + PADF;                  // P[x], x can be negative to -64

    #pragma unroll
    for (int g = 0; g < 3; g++) {
        const int q = 3 * stripe + g;             // d-group: d = 4q+s, s=0..3
        // Two aligned 16B smem loads cover all 4 disparities of this group.
        const float4 Y = *reinterpret_cast<const float4*>(P + 4 * (c - q));
        const float4 X = *reinterpret_cast<const float4*>(P + 4 * (c - q - 1));
        const float yv[4] = {Y.x, Y.y, Y.z, Y.w};
        const float xv[4] = {X.x, X.y, X.z, X.w};

        #pragma unroll
        for (int s = 0; s < 4; s++) {
            const int d = 4 * q + s;
            float4 v;
            // out[4c+i] uses P[4c+i-d] = (i>=s) ? Y[i-s] : X[i+4-s]  (static)
            v.x = l4.x * ((0 >= s) ? yv[0 - s < 0 ? 0 : 0 - s] : xv[0 + 4 - s]);
            v.y = l4.y * ((1 >= s) ? yv[(1 - s) & 3] : xv[1 + 4 - s]);
            v.z = l4.z * ((2 >= s) ? yv[(2 - s) & 3] : xv[2 + 4 - s]);
            v.w = l4.w * ((3 >= s) ? yv[(3 - s) & 3] : xv[3 + 4 - s]);
            __stcs(reinterpret_cast<float4*>(obase + (size_t)d * (NH * NW)), v);
        }
    }
}

extern "C" void kernel_launch(void* const* d_in, const int* in_sizes, int n_in,
                              void* d_out, int out_size) {
    const float* left  = (const float*)d_in[0];
    const float* right = (const float*)d_in[1];
    float* out = (float*)d_out;

    const int grid = NN * NC * NH;       // 8704 CTAs, one per (n,c,h) row
    cost_volume_kernel<<<grid, THREADS>>>(left, right, out);
}